// round 1
// baseline (speedup 1.0000x reference)
#include <cuda_runtime.h>
#include <stdint.h>

#define NBATCH 8
#define NB1    2048
#define CAPLOG 19
#define CAP    (1u << CAPLOG)   // 524288 candidates per batch (bucket holds ~163K)

// ---- static scratch (no allocations allowed) ----
__device__ unsigned g_hist1[NBATCH][NB1];
__device__ unsigned g_candCount[NBATCH];
__device__ uint2    g_cand[NBATCH][CAP];   // (key, index-within-batch)
__device__ unsigned g_b1[NBATCH];
__device__ unsigned g_r1[NBATCH];
__device__ unsigned g_Tkey[NBATCH];

// order-preserving float->uint key (larger float => larger key)
__device__ __forceinline__ unsigned fkey(float f) {
    unsigned u = __float_as_uint(f);
    return (u & 0x80000000u) ? ~u : (u | 0x80000000u);
}
__device__ __forceinline__ float keyf(unsigned k) {
    return __uint_as_float((k & 0x80000000u) ? (k ^ 0x80000000u) : ~k);
}

// ---------------- K0: zero scratch counters ----------------
__global__ void k_zero() {
    int i = blockIdx.x * blockDim.x + threadIdx.x;
    int total = NBATCH * NB1;
    if (i < total) ((unsigned*)g_hist1)[i] = 0u;
    if (i < NBATCH) g_candCount[i] = 0u;
}

// ---------------- K1: coarse histogram (top 11 key bits) ----------------
__global__ void k_hist(const float4* __restrict__ in, int N4) {
    __shared__ unsigned h[NB1];
    int tid = threadIdx.x;
    for (int j = tid; j < NB1; j += blockDim.x) h[j] = 0u;
    __syncthreads();

    int b = blockIdx.y;
    size_t base = (size_t)b * (size_t)N4;
    int stride = gridDim.x * blockDim.x;
    for (int i = blockIdx.x * blockDim.x + tid; i < N4; i += stride) {
        float4 v = in[base + i];
        atomicAdd(&h[fkey(v.x) >> 21], 1u);
        atomicAdd(&h[fkey(v.y) >> 21], 1u);
        atomicAdd(&h[fkey(v.z) >> 21], 1u);
        atomicAdd(&h[fkey(v.w) >> 21], 1u);
    }
    __syncthreads();
    for (int j = tid; j < NB1; j += blockDim.x)
        if (h[j]) atomicAdd(&g_hist1[b][j], h[j]);
}

// ---------------- K2: find coarse bucket + residual rank ----------------
__global__ void k_select1(unsigned k) {
    __shared__ unsigned s[256];
    int b = blockIdx.x, tid = threadIdx.x;
    unsigned part = 0;
#pragma unroll
    for (int d = 0; d < 8; ++d) part += g_hist1[b][tid * 8 + d];
    s[tid] = part;
    __syncthreads();
    for (int off = 1; off < 256; off <<= 1) {
        unsigned v = (tid + off < 256) ? s[tid + off] : 0u;
        __syncthreads();
        s[tid] += v;
        __syncthreads();
    }
    unsigned above = (tid == 255) ? 0u : s[tid + 1];
    if (s[tid] >= k && above < k) {
        unsigned acc = above;
        for (int bin = tid * 8 + 7; bin >= tid * 8; --bin) {
            unsigned c = g_hist1[b][bin];
            if (k <= acc + c) { g_b1[b] = (unsigned)bin; g_r1[b] = k - acc; break; }
            acc += c;
        }
    }
}

// ---------------- K3: fused mask + candidate compaction ----------------
__global__ void k_mask(const float4* __restrict__ in, float4* __restrict__ out, int N4) {
    int b = blockIdx.y;
    unsigned b1 = g_b1[b];
    size_t base = (size_t)b * (size_t)N4;
    int tid = threadIdx.x;
    int lane = tid & 31;
    int stride = gridDim.x * blockDim.x;
    int nIter = (N4 + stride - 1) / stride;
    int i0 = blockIdx.x * blockDim.x + tid;

    for (int it = 0; it < nIter; ++it) {
        int i = i0 + it * stride;
        bool valid = (i < N4);
        float4 v = valid ? in[base + i] : make_float4(0.f, 0.f, 0.f, 0.f);
        float4 o;
        float* vp = &v.x;
        float* op = &o.x;
#pragma unroll
        for (int c = 0; c < 4; ++c) {
            unsigned key = fkey(vp[c]);
            unsigned t11 = key >> 21;
            op[c] = (valid && t11 > b1) ? vp[c] : 0.f;
            bool p = valid && (t11 == b1);
            unsigned m = __ballot_sync(0xffffffffu, p);
            if (m) {
                int leader = __ffs(m) - 1;
                unsigned pos = 0;
                if (lane == leader) pos = atomicAdd(&g_candCount[b], (unsigned)__popc(m));
                pos = __shfl_sync(0xffffffffu, pos, leader);
                pos += (unsigned)__popc(m & ((1u << lane) - 1u));
                if (p && pos < CAP)
                    g_cand[b][pos] = make_uint2(key, (unsigned)(i * 4 + c));
            }
        }
        if (valid) out[base + i] = o;
    }
}

// ---------------- K4: exact select within bucket + tie resolution ----------------
__global__ void k_select2(float* __restrict__ out, int N) {
    __shared__ unsigned h[2048];
    __shared__ unsigned s[1024];
    __shared__ unsigned res[6]; // b2, r2, b3, r, cnt_eq, eqCount
    int b = blockIdx.x, tid = threadIdx.x;
    unsigned m = min(g_candCount[b], CAP);
    unsigned r1 = g_r1[b];

    // Level 2: 1024 bins on key bits [20:11]
    h[tid] = 0u;
    __syncthreads();
    for (unsigned j = tid; j < m; j += 1024)
        atomicAdd(&h[(g_cand[b][j].x >> 11) & 0x3FFu], 1u);
    __syncthreads();
    s[tid] = h[tid];
    __syncthreads();
    for (int off = 1; off < 1024; off <<= 1) {
        unsigned v = (tid + off < 1024) ? s[tid + off] : 0u;
        __syncthreads();
        s[tid] += v;
        __syncthreads();
    }
    {
        unsigned above = (tid == 1023) ? 0u : s[tid + 1];
        if (s[tid] >= r1 && above < r1) { res[0] = (unsigned)tid; res[1] = r1 - above; }
    }
    __syncthreads();
    unsigned b2 = res[0], r2 = res[1];

    // Level 3: 2048 bins on key bits [10:0] within bucket2
    h[tid] = 0u; h[tid + 1024] = 0u;
    __syncthreads();
    for (unsigned j = tid; j < m; j += 1024) {
        unsigned key = g_cand[b][j].x;
        if (((key >> 11) & 0x3FFu) == b2) atomicAdd(&h[key & 0x7FFu], 1u);
    }
    __syncthreads();
    s[tid] = h[2 * tid] + h[2 * tid + 1];
    __syncthreads();
    for (int off = 1; off < 1024; off <<= 1) {
        unsigned v = (tid + off < 1024) ? s[tid + off] : 0u;
        __syncthreads();
        s[tid] += v;
        __syncthreads();
    }
    {
        unsigned above = (tid == 1023) ? 0u : s[tid + 1];
        if (s[tid] >= r2 && above < r2) {
            unsigned hi = h[2 * tid + 1];
            if (r2 <= above + hi) { res[2] = 2u * tid + 1u; res[3] = r2 - above; res[4] = hi; }
            else { res[2] = 2u * tid; res[3] = r2 - above - hi; res[4] = h[2 * tid]; }
        }
    }
    if (tid == 0) res[5] = 0u;
    __syncthreads();

    unsigned b3 = res[2];
    unsigned Tkey = (g_b1[b] << 21) | (b2 << 11) | b3;
    if (tid == 0) g_Tkey[b] = Tkey;
    unsigned r = res[3];

    // collect indices of elements == Tkey (reuse h as index buffer)
    for (unsigned j = tid; j < m; j += 1024) {
        uint2 e = g_cand[b][j];
        if (e.x == Tkey) {
            unsigned p = atomicAdd(&res[5], 1u);
            if (p < 2048u) h[p] = e.y;
        }
    }
    __syncthreads();
    unsigned ne = min(res[5], 2048u);
    float tv = keyf(Tkey);
    // keep the r smallest indices among equals (matches top_k tie-breaking)
    for (unsigned j = tid; j < ne; j += 1024) {
        unsigned my = h[j];
        unsigned rank = 0;
        for (unsigned q = 0; q < ne; ++q) rank += (h[q] < my) ? 1u : 0u;
        if (rank < r) out[(size_t)b * (size_t)N + my] = tv;
    }
}

// ---------------- K5: write back candidates strictly above threshold ----------------
__global__ void k_fix(float* __restrict__ out, int N) {
    int b = blockIdx.y;
    unsigned count = min(g_candCount[b], CAP);
    unsigned Tkey = g_Tkey[b];
    int stride = gridDim.x * blockDim.x;
    for (unsigned j = blockIdx.x * blockDim.x + threadIdx.x; j < count; j += stride) {
        uint2 e = g_cand[b][j];
        if (e.x > Tkey) out[(size_t)b * (size_t)N + e.y] = keyf(e.x);
    }
}

extern "C" void kernel_launch(void* const* d_in, const int* in_sizes, int n_in,
                              void* d_out, int out_size) {
    const float* in = (const float*)d_in[0];
    float* out = (float*)d_out;
    int total = in_sizes[0];
    int N = total / NBATCH;           // 4,194,304
    int N4 = N / 4;
    unsigned k = (unsigned)(0.1 * (double)N);
    if (k < 1u) k = 1u;

    k_zero<<<17, 1024>>>();
    k_hist<<<dim3(32, NBATCH), 512>>>((const float4*)in, N4);
    k_select1<<<NBATCH, 256>>>(k);
    k_mask<<<dim3(32, NBATCH), 512>>>((const float4*)in, (float4*)out, N4);
    k_select2<<<NBATCH, 1024>>>(out, N);
    k_fix<<<dim3(64, NBATCH), 256>>>(out, N);
}

// round 2
// speedup vs baseline: 1.0296x; 1.0296x over previous
#include <cuda_runtime.h>
#include <stdint.h>

#define NBATCH 8
#define NB1    2048
#define CAPLOG 19
#define CAP    (1u << CAPLOG)   // 524288 candidates per batch (bucket holds ~163K)

// ---- static scratch (no allocations allowed) ----
__device__ unsigned g_hist1[NBATCH][NB1];
__device__ unsigned g_candCount[NBATCH];
__device__ uint2    g_cand[NBATCH][CAP];   // (key, index-within-batch)
__device__ unsigned g_b1[NBATCH];
__device__ unsigned g_r1[NBATCH];
__device__ unsigned g_Tkey[NBATCH];

// order-preserving float->uint key (larger float => larger key)
__device__ __forceinline__ unsigned fkey(float f) {
    unsigned u = __float_as_uint(f);
    return (u & 0x80000000u) ? ~u : (u | 0x80000000u);
}
__device__ __forceinline__ float keyf(unsigned k) {
    return __uint_as_float((k & 0x80000000u) ? (k ^ 0x80000000u) : ~k);
}

// ---------------- K0: zero scratch counters ----------------
__global__ void k_zero() {
    int i = blockIdx.x * blockDim.x + threadIdx.x;
    int total = NBATCH * NB1;
    if (i < total) ((unsigned*)g_hist1)[i] = 0u;
    if (i < NBATCH) g_candCount[i] = 0u;
}

// ---------------- K1: coarse histogram (top 11 key bits) ----------------
// 256 blocks/batch x 256 threads; 4-deep load batching for MLP.
__global__ void k_hist(const float4* __restrict__ in, int N4) {
    __shared__ unsigned h[NB1];
    int tid = threadIdx.x;
    for (int j = tid; j < NB1; j += blockDim.x) h[j] = 0u;
    __syncthreads();

    int b = blockIdx.y;
    size_t base = (size_t)b * (size_t)N4;
    int stride = gridDim.x * blockDim.x;
    int i0 = blockIdx.x * blockDim.x + tid;

    for (int off = 0; off < N4; off += 4 * stride) {
        float4 v[4];
        bool valid[4];
#pragma unroll
        for (int t = 0; t < 4; ++t) {
            int i = i0 + off + t * stride;
            valid[t] = (i < N4);
            v[t] = valid[t] ? in[base + i] : make_float4(0.f, 0.f, 0.f, 0.f);
        }
#pragma unroll
        for (int t = 0; t < 4; ++t) {
            if (!valid[t]) continue;
            atomicAdd(&h[fkey(v[t].x) >> 21], 1u);
            atomicAdd(&h[fkey(v[t].y) >> 21], 1u);
            atomicAdd(&h[fkey(v[t].z) >> 21], 1u);
            atomicAdd(&h[fkey(v[t].w) >> 21], 1u);
        }
    }
    __syncthreads();
    for (int j = tid; j < NB1; j += blockDim.x)
        if (h[j]) atomicAdd(&g_hist1[b][j], h[j]);
}

// ---------------- K2: find coarse bucket + residual rank ----------------
__global__ void k_select1(unsigned k) {
    __shared__ unsigned s[256];
    int b = blockIdx.x, tid = threadIdx.x;
    unsigned part = 0;
#pragma unroll
    for (int d = 0; d < 8; ++d) part += g_hist1[b][tid * 8 + d];
    s[tid] = part;
    __syncthreads();
    for (int off = 1; off < 256; off <<= 1) {
        unsigned v = (tid + off < 256) ? s[tid + off] : 0u;
        __syncthreads();
        s[tid] += v;
        __syncthreads();
    }
    unsigned above = (tid == 255) ? 0u : s[tid + 1];
    if (s[tid] >= k && above < k) {
        unsigned acc = above;
        for (int bin = tid * 8 + 7; bin >= tid * 8; --bin) {
            unsigned c = g_hist1[b][bin];
            if (k <= acc + c) { g_b1[b] = (unsigned)bin; g_r1[b] = k - acc; break; }
            acc += c;
        }
    }
}

// ---------------- K3: fused mask + candidate compaction ----------------
// 512 blocks/batch x 256 threads; preload 8 float4 per thread (MLP=8),
// then do all ballots/atomics/stores on registers.
#define MITER 8
__global__ void k_mask(const float4* __restrict__ in, float4* __restrict__ out, int N4) {
    int b = blockIdx.y;
    unsigned b1 = g_b1[b];
    size_t base = (size_t)b * (size_t)N4;
    int tid = threadIdx.x;
    int lane = tid & 31;
    int stride = gridDim.x * blockDim.x;
    int i0 = blockIdx.x * blockDim.x + tid;

    for (int off = 0; off < N4; off += MITER * stride) {
        float4 v[MITER];
        bool valid[MITER];
#pragma unroll
        for (int t = 0; t < MITER; ++t) {
            int i = i0 + off + t * stride;
            valid[t] = (i < N4);
            v[t] = valid[t] ? in[base + i] : make_float4(0.f, 0.f, 0.f, 0.f);
        }
#pragma unroll
        for (int t = 0; t < MITER; ++t) {
            int i = i0 + off + t * stride;
            float4 o;
            float* vp = &v[t].x;
            float* op = &o.x;
#pragma unroll
            for (int c = 0; c < 4; ++c) {
                unsigned key = fkey(vp[c]);
                unsigned t11 = key >> 21;
                op[c] = (valid[t] && t11 > b1) ? vp[c] : 0.f;
                bool p = valid[t] && (t11 == b1);
                unsigned m = __ballot_sync(0xffffffffu, p);
                if (m) {
                    int leader = __ffs(m) - 1;
                    unsigned pos = 0;
                    if (lane == leader) pos = atomicAdd(&g_candCount[b], (unsigned)__popc(m));
                    pos = __shfl_sync(0xffffffffu, pos, leader);
                    pos += (unsigned)__popc(m & ((1u << lane) - 1u));
                    if (p && pos < CAP)
                        g_cand[b][pos] = make_uint2(key, (unsigned)(i * 4 + c));
                }
            }
            if (valid[t]) out[base + i] = o;
        }
    }
}

// ---------------- K4: exact select within bucket + tie resolution ----------------
__global__ void k_select2(float* __restrict__ out, int N) {
    __shared__ unsigned h[2048];
    __shared__ unsigned s[1024];
    __shared__ unsigned res[6]; // b2, r2, b3, r, cnt_eq, eqCount
    int b = blockIdx.x, tid = threadIdx.x;
    unsigned m = min(g_candCount[b], CAP);
    unsigned r1 = g_r1[b];

    // Level 2: 1024 bins on key bits [20:11]
    h[tid] = 0u;
    __syncthreads();
    for (unsigned j = tid; j < m; j += 1024)
        atomicAdd(&h[(g_cand[b][j].x >> 11) & 0x3FFu], 1u);
    __syncthreads();
    s[tid] = h[tid];
    __syncthreads();
    for (int off = 1; off < 1024; off <<= 1) {
        unsigned v = (tid + off < 1024) ? s[tid + off] : 0u;
        __syncthreads();
        s[tid] += v;
        __syncthreads();
    }
    {
        unsigned above = (tid == 1023) ? 0u : s[tid + 1];
        if (s[tid] >= r1 && above < r1) { res[0] = (unsigned)tid; res[1] = r1 - above; }
    }
    __syncthreads();
    unsigned b2 = res[0], r2 = res[1];

    // Level 3: 2048 bins on key bits [10:0] within bucket2
    h[tid] = 0u; h[tid + 1024] = 0u;
    __syncthreads();
    for (unsigned j = tid; j < m; j += 1024) {
        unsigned key = g_cand[b][j].x;
        if (((key >> 11) & 0x3FFu) == b2) atomicAdd(&h[key & 0x7FFu], 1u);
    }
    __syncthreads();
    s[tid] = h[2 * tid] + h[2 * tid + 1];
    __syncthreads();
    for (int off = 1; off < 1024; off <<= 1) {
        unsigned v = (tid + off < 1024) ? s[tid + off] : 0u;
        __syncthreads();
        s[tid] += v;
        __syncthreads();
    }
    {
        unsigned above = (tid == 1023) ? 0u : s[tid + 1];
        if (s[tid] >= r2 && above < r2) {
            unsigned hi = h[2 * tid + 1];
            if (r2 <= above + hi) { res[2] = 2u * tid + 1u; res[3] = r2 - above; res[4] = hi; }
            else { res[2] = 2u * tid; res[3] = r2 - above - hi; res[4] = h[2 * tid]; }
        }
    }
    if (tid == 0) res[5] = 0u;
    __syncthreads();

    unsigned b3 = res[2];
    unsigned Tkey = (g_b1[b] << 21) | (b2 << 11) | b3;
    if (tid == 0) g_Tkey[b] = Tkey;
    unsigned r = res[3];

    // collect indices of elements == Tkey (reuse h as index buffer)
    for (unsigned j = tid; j < m; j += 1024) {
        uint2 e = g_cand[b][j];
        if (e.x == Tkey) {
            unsigned p = atomicAdd(&res[5], 1u);
            if (p < 2048u) h[p] = e.y;
        }
    }
    __syncthreads();
    unsigned ne = min(res[5], 2048u);
    float tv = keyf(Tkey);
    // keep the r smallest indices among equals (matches top_k tie-breaking)
    for (unsigned j = tid; j < ne; j += 1024) {
        unsigned my = h[j];
        unsigned rank = 0;
        for (unsigned q = 0; q < ne; ++q) rank += (h[q] < my) ? 1u : 0u;
        if (rank < r) out[(size_t)b * (size_t)N + my] = tv;
    }
}

// ---------------- K5: write back candidates strictly above threshold ----------------
__global__ void k_fix(float* __restrict__ out, int N) {
    int b = blockIdx.y;
    unsigned count = min(g_candCount[b], CAP);
    unsigned Tkey = g_Tkey[b];
    int stride = gridDim.x * blockDim.x;
    for (unsigned j = blockIdx.x * blockDim.x + threadIdx.x; j < count; j += stride) {
        uint2 e = g_cand[b][j];
        if (e.x > Tkey) out[(size_t)b * (size_t)N + e.y] = keyf(e.x);
    }
}

extern "C" void kernel_launch(void* const* d_in, const int* in_sizes, int n_in,
                              void* d_out, int out_size) {
    const float* in = (const float*)d_in[0];
    float* out = (float*)d_out;
    int total = in_sizes[0];
    int N = total / NBATCH;           // 4,194,304
    int N4 = N / 4;
    unsigned k = (unsigned)(0.1 * (double)N);
    if (k < 1u) k = 1u;

    k_zero<<<17, 1024>>>();
    k_hist<<<dim3(256, NBATCH), 256>>>((const float4*)in, N4);
    k_select1<<<NBATCH, 256>>>(k);
    k_mask<<<dim3(512, NBATCH), 256>>>((const float4*)in, (float4*)out, N4);
    k_select2<<<NBATCH, 1024>>>(out, N);
    k_fix<<<dim3(256, NBATCH), 256>>>(out, N);
}

// round 4
// speedup vs baseline: 3.9256x; 3.8127x over previous
#include <cuda_runtime.h>
#include <stdint.h>

#define NBATCH 8
#define NB1    2048
#define CAPLOG 19
#define CAP    (1u << CAPLOG)   // 524288 candidates per batch

// ---- static scratch (no allocations allowed) ----
__device__ unsigned g_hist1[NBATCH][NB1];
__device__ unsigned g_candCount[NBATCH];
__device__ uint2    g_cand[NBATCH][CAP];   // (key, index-within-batch)
__device__ unsigned g_b1[NBATCH];
__device__ unsigned g_r1[NBATCH];
__device__ unsigned g_Tkey[NBATCH];

__device__ __forceinline__ unsigned fkey(float f) {
    unsigned u = __float_as_uint(f);
    return (u & 0x80000000u) ? ~u : (u | 0x80000000u);
}
__device__ __forceinline__ float keyf(unsigned k) {
    return __uint_as_float((k & 0x80000000u) ? (k ^ 0x80000000u) : ~k);
}

// ---------------- K0: zero scratch counters ----------------
__global__ void k_zero() {
    int i = blockIdx.x * blockDim.x + threadIdx.x;
    int total = NBATCH * NB1;
    if (i < total) ((unsigned*)g_hist1)[i] = 0u;
    if (i < NBATCH) g_candCount[i] = 0u;
}

// ---------------- K1: coarse histogram (top 11 key bits) ----------------
// 4-way replicated smem histograms to cut hot-bin atomic conflicts.
__global__ void k_hist(const float4* __restrict__ in, int N4) {
    __shared__ unsigned h[4][NB1];   // 32 KB
    int tid = threadIdx.x;
    for (int j = tid; j < 4 * NB1; j += blockDim.x) ((unsigned*)h)[j] = 0u;
    __syncthreads();

    int b = blockIdx.y;
    int sub = (tid >> 5) & 3;
    size_t base = (size_t)b * (size_t)N4;
    int stride = gridDim.x * blockDim.x;
    int i0 = blockIdx.x * blockDim.x + tid;

    for (int off = 0; off < N4; off += 4 * stride) {
        float4 v[4];
        bool valid[4];
#pragma unroll
        for (int t = 0; t < 4; ++t) {
            int i = i0 + off + t * stride;
            valid[t] = (i < N4);
            v[t] = valid[t] ? in[base + i] : make_float4(0.f, 0.f, 0.f, 0.f);
        }
#pragma unroll
        for (int t = 0; t < 4; ++t) {
            if (!valid[t]) continue;
            atomicAdd(&h[sub][fkey(v[t].x) >> 21], 1u);
            atomicAdd(&h[sub][fkey(v[t].y) >> 21], 1u);
            atomicAdd(&h[sub][fkey(v[t].z) >> 21], 1u);
            atomicAdd(&h[sub][fkey(v[t].w) >> 21], 1u);
        }
    }
    __syncthreads();
    for (int j = tid; j < NB1; j += blockDim.x) {
        unsigned s = h[0][j] + h[1][j] + h[2][j] + h[3][j];
        if (s) atomicAdd(&g_hist1[b][j], s);
    }
}

// ---------------- K2: find coarse bucket + residual rank ----------------
__global__ void k_select1(unsigned k) {
    __shared__ unsigned s[256];
    int b = blockIdx.x, tid = threadIdx.x;
    unsigned part = 0;
#pragma unroll
    for (int d = 0; d < 8; ++d) part += g_hist1[b][tid * 8 + d];
    s[tid] = part;
    __syncthreads();
    for (int off = 1; off < 256; off <<= 1) {
        unsigned v = (tid + off < 256) ? s[tid + off] : 0u;
        __syncthreads();
        s[tid] += v;
        __syncthreads();
    }
    unsigned above = (tid == 255) ? 0u : s[tid + 1];
    if (s[tid] >= k && above < k) {
        unsigned acc = above;
        for (int bin = tid * 8 + 7; bin >= tid * 8; --bin) {
            unsigned c = g_hist1[b][bin];
            if (k <= acc + c) { g_b1[b] = (unsigned)bin; g_r1[b] = k - acc; break; }
            acc += c;
        }
    }
}

// ---------------- K3: fused mask + candidate compaction ----------------
// NO atomics/ballots in the hot loop. Each thread buffers candidates locally,
// then one warp-scan + one atomicAdd per warp at the end.
#define MITER 8
__global__ void k_mask(const float4* __restrict__ in, float4* __restrict__ out, int N4) {
    int b = blockIdx.y;
    unsigned b1 = g_b1[b];
    size_t base = (size_t)b * (size_t)N4;
    int tid = threadIdx.x;
    int lane = tid & 31;
    int stride = gridDim.x * blockDim.x;
    int i0 = blockIdx.x * blockDim.x + tid;

    uint2 lbuf[MITER * 4];
    unsigned cnt = 0;

    for (int off = 0; off < N4; off += MITER * stride) {
        float4 v[MITER];
        bool valid[MITER];
#pragma unroll
        for (int t = 0; t < MITER; ++t) {
            int i = i0 + off + t * stride;
            valid[t] = (i < N4);
            v[t] = valid[t] ? in[base + i] : make_float4(0.f, 0.f, 0.f, 0.f);
        }
#pragma unroll
        for (int t = 0; t < MITER; ++t) {
            int i = i0 + off + t * stride;
            float4 o;
            float* vp = &v[t].x;
            float* op = &o.x;
#pragma unroll
            for (int c = 0; c < 4; ++c) {
                unsigned key = fkey(vp[c]);
                unsigned t11 = key >> 21;
                op[c] = (t11 > b1) ? vp[c] : 0.f;
                if (valid[t] && t11 == b1 && cnt < MITER * 4u)
                    lbuf[cnt++] = make_uint2(key, (unsigned)(i * 4 + c));
            }
            if (valid[t]) out[base + i] = o;
        }
    }

    // warp-aggregated candidate flush: inclusive shfl scan of counts
    unsigned inc = cnt;
#pragma unroll
    for (int d = 1; d < 32; d <<= 1) {
        unsigned n = __shfl_up_sync(0xffffffffu, inc, d);
        if (lane >= d) inc += n;
    }
    unsigned total = __shfl_sync(0xffffffffu, inc, 31);
    unsigned basepos = 0;
    if (lane == 31 && total) basepos = atomicAdd(&g_candCount[b], total);
    basepos = __shfl_sync(0xffffffffu, basepos, 31);
    unsigned mystart = basepos + inc - cnt;
    for (unsigned j = 0; j < cnt; ++j) {
        unsigned p = mystart + j;
        if (p < CAP) g_cand[b][p] = lbuf[j];
    }
}

// ---------------- K4: exact select within bucket + tie resolution ----------------
__global__ void k_select2(float* __restrict__ out, int N) {
    __shared__ unsigned h[2048];
    __shared__ unsigned s[1024];
    __shared__ unsigned res[6];
    int b = blockIdx.x, tid = threadIdx.x;
    unsigned m = min(g_candCount[b], CAP);
    unsigned r1 = g_r1[b];

    // Level 2: 1024 bins on key bits [20:11]
    h[tid] = 0u;
    __syncthreads();
    for (unsigned j = tid; j < m; j += 1024)
        atomicAdd(&h[(g_cand[b][j].x >> 11) & 0x3FFu], 1u);
    __syncthreads();
    s[tid] = h[tid];
    __syncthreads();
    for (int off = 1; off < 1024; off <<= 1) {
        unsigned v = (tid + off < 1024) ? s[tid + off] : 0u;
        __syncthreads();
        s[tid] += v;
        __syncthreads();
    }
    {
        unsigned above = (tid == 1023) ? 0u : s[tid + 1];
        if (s[tid] >= r1 && above < r1) { res[0] = (unsigned)tid; res[1] = r1 - above; }
    }
    __syncthreads();
    unsigned b2 = res[0], r2 = res[1];

    // Level 3: 2048 bins on key bits [10:0] within bucket2
    h[tid] = 0u; h[tid + 1024] = 0u;
    __syncthreads();
    for (unsigned j = tid; j < m; j += 1024) {
        unsigned key = g_cand[b][j].x;
        if (((key >> 11) & 0x3FFu) == b2) atomicAdd(&h[key & 0x7FFu], 1u);
    }
    __syncthreads();
    s[tid] = h[2 * tid] + h[2 * tid + 1];
    __syncthreads();
    for (int off = 1; off < 1024; off <<= 1) {
        unsigned v = (tid + off < 1024) ? s[tid + off] : 0u;
        __syncthreads();
        s[tid] += v;
        __syncthreads();
    }
    {
        unsigned above = (tid == 1023) ? 0u : s[tid + 1];
        if (s[tid] >= r2 && above < r2) {
            unsigned hi = h[2 * tid + 1];
            if (r2 <= above + hi) { res[2] = 2u * tid + 1u; res[3] = r2 - above; res[4] = hi; }
            else { res[2] = 2u * tid; res[3] = r2 - above - hi; res[4] = h[2 * tid]; }
        }
    }
    if (tid == 0) res[5] = 0u;
    __syncthreads();

    unsigned b3 = res[2];
    unsigned Tkey = (g_b1[b] << 21) | (b2 << 11) | b3;
    if (tid == 0) g_Tkey[b] = Tkey;
    unsigned r = res[3];

    // collect indices of elements == Tkey (reuse h as index buffer)
    for (unsigned j = tid; j < m; j += 1024) {
        uint2 e = g_cand[b][j];
        if (e.x == Tkey) {
            unsigned p = atomicAdd(&res[5], 1u);
            if (p < 2048u) h[p] = e.y;
        }
    }
    __syncthreads();
    unsigned ne = min(res[5], 2048u);
    float tv = keyf(Tkey);
    for (unsigned j = tid; j < ne; j += 1024) {
        unsigned my = h[j];
        unsigned rank = 0;
        for (unsigned q = 0; q < ne; ++q) rank += (h[q] < my) ? 1u : 0u;
        if (rank < r) out[(size_t)b * (size_t)N + my] = tv;
    }
}

// ---------------- K5: write back candidates strictly above threshold ----------------
__global__ void k_fix(float* __restrict__ out, int N) {
    int b = blockIdx.y;
    unsigned count = min(g_candCount[b], CAP);
    unsigned Tkey = g_Tkey[b];
    int stride = gridDim.x * blockDim.x;
    for (unsigned j = blockIdx.x * blockDim.x + threadIdx.x; j < count; j += stride) {
        uint2 e = g_cand[b][j];
        if (e.x > Tkey) out[(size_t)b * (size_t)N + e.y] = keyf(e.x);
    }
}

extern "C" void kernel_launch(void* const* d_in, const int* in_sizes, int n_in,
                              void* d_out, int out_size) {
    const float* in = (const float*)d_in[0];
    float* out = (float*)d_out;
    int total = in_sizes[0];
    int N = total / NBATCH;
    int N4 = N / 4;
    unsigned k = (unsigned)(0.1 * (double)N);
    if (k < 1u) k = 1u;

    k_zero<<<17, 1024>>>();
    k_hist<<<dim3(256, NBATCH), 256>>>((const float4*)in, N4);
    k_select1<<<NBATCH, 256>>>(k);
    k_mask<<<dim3(512, NBATCH), 256>>>((const float4*)in, (float4*)out, N4);
    k_select2<<<NBATCH, 1024>>>(out, N);
    k_fix<<<dim3(256, NBATCH), 256>>>(out, N);
}

// round 5
// speedup vs baseline: 4.6194x; 1.1767x over previous
#include <cuda_runtime.h>
#include <stdint.h>

#define NBATCH 8
#define NB1    2048
#define CAPLOG 19
#define CAP    (1u << CAPLOG)   // 524288 candidates per batch

// ---- static scratch (no allocations allowed) ----
__device__ unsigned g_hist1[NBATCH][NB1];
__device__ unsigned g_hist2[NBATCH][1024];
__device__ unsigned g_hist3[NBATCH][2048];
__device__ unsigned g_candCount[NBATCH];
__device__ uint2    g_cand[NBATCH][CAP];
__device__ unsigned g_b1[NBATCH], g_r1[NBATCH];
__device__ unsigned g_b2[NBATCH], g_r2[NBATCH];
__device__ unsigned g_Tkey[NBATCH], g_r3[NBATCH];
__device__ float    g_Tlo[NBATCH], g_Thi[NBATCH];
__device__ unsigned g_eqCount[NBATCH];
__device__ unsigned g_eqIdx[NBATCH][4096];

__device__ __forceinline__ unsigned fkey(float f) {
    unsigned u = __float_as_uint(f);
    return (u & 0x80000000u) ? ~u : (u | 0x80000000u);
}
__device__ __forceinline__ float keyf(unsigned k) {
    return __uint_as_float((k & 0x80000000u) ? (k ^ 0x80000000u) : ~k);
}

// ---------------- K0: zero all counters ----------------
__global__ void k_zero() {
    int i = blockIdx.x * blockDim.x + threadIdx.x;
    if (i < NBATCH * NB1)  ((unsigned*)g_hist1)[i] = 0u;
    if (i < NBATCH * 1024) ((unsigned*)g_hist2)[i] = 0u;
    if (i < NBATCH * 2048) ((unsigned*)g_hist3)[i] = 0u;
    if (i < NBATCH) { g_candCount[i] = 0u; g_eqCount[i] = 0u; }
}

// ---------------- K1: coarse histogram (top 11 key bits), MLP-8 ----------------
__global__ void k_hist(const float4* __restrict__ in, int N4) {
    __shared__ unsigned h[4][NB1];   // 32 KB, 4-way replicated
    int tid = threadIdx.x;
    for (int j = tid; j < 4 * NB1; j += blockDim.x) ((unsigned*)h)[j] = 0u;
    __syncthreads();

    int b = blockIdx.y;
    int sub = (tid >> 5) & 3;
    size_t base = (size_t)b * (size_t)N4;
    int stride = gridDim.x * blockDim.x;
    int i0 = blockIdx.x * blockDim.x + tid;

    for (int off = 0; off < N4; off += 8 * stride) {
        float4 v[8];
        bool valid[8];
#pragma unroll
        for (int t = 0; t < 8; ++t) {
            int i = i0 + off + t * stride;
            valid[t] = (i < N4);
            v[t] = valid[t] ? in[base + i] : make_float4(0.f, 0.f, 0.f, 0.f);
        }
#pragma unroll
        for (int t = 0; t < 8; ++t) {
            if (!valid[t]) continue;
            atomicAdd(&h[sub][fkey(v[t].x) >> 21], 1u);
            atomicAdd(&h[sub][fkey(v[t].y) >> 21], 1u);
            atomicAdd(&h[sub][fkey(v[t].z) >> 21], 1u);
            atomicAdd(&h[sub][fkey(v[t].w) >> 21], 1u);
        }
    }
    __syncthreads();
    for (int j = tid; j < NB1; j += blockDim.x) {
        unsigned s = h[0][j] + h[1][j] + h[2][j] + h[3][j];
        if (s) atomicAdd(&g_hist1[b][j], s);
    }
}

// ---------------- K2: coarse bucket + residual rank + float bounds ----------------
__global__ void k_select1(unsigned k) {
    __shared__ unsigned s[256];
    int b = blockIdx.x, tid = threadIdx.x;
    unsigned part = 0;
#pragma unroll
    for (int d = 0; d < 8; ++d) part += g_hist1[b][tid * 8 + d];
    s[tid] = part;
    __syncthreads();
    for (int off = 1; off < 256; off <<= 1) {
        unsigned v = (tid + off < 256) ? s[tid + off] : 0u;
        __syncthreads();
        s[tid] += v;
        __syncthreads();
    }
    unsigned above = (tid == 255) ? 0u : s[tid + 1];
    if (s[tid] >= k && above < k) {
        unsigned acc = above;
        for (int bin = tid * 8 + 7; bin >= tid * 8; --bin) {
            unsigned c = g_hist1[b][bin];
            if (k <= acc + c) {
                g_b1[b] = (unsigned)bin;
                g_r1[b] = k - acc;
                g_Tlo[b] = keyf(((unsigned)bin) << 21);
                g_Thi[b] = keyf((((unsigned)bin) << 21) | 0x1FFFFFu);
                break;
            }
            acc += c;
        }
    }
}

// ---------------- K3: fused mask + candidate compaction ----------------
// float-compare fast path; fkey only on the rare candidate path.
// __ldcs reads + __stcs writes so output traffic doesn't evict k_hist's
// L2-resident input.
#define MITER 8
__global__ void k_mask(const float4* __restrict__ in, float4* __restrict__ out, int N4) {
    int b = blockIdx.y;
    float Tlo = g_Tlo[b], Thi = g_Thi[b];
    size_t base = (size_t)b * (size_t)N4;
    int tid = threadIdx.x;
    int lane = tid & 31;
    int stride = gridDim.x * blockDim.x;
    int i0 = blockIdx.x * blockDim.x + tid;

    uint2 lbuf[MITER * 4];
    unsigned cnt = 0;

    for (int off = 0; off < N4; off += MITER * stride) {
        float4 v[MITER];
        bool valid[MITER];
#pragma unroll
        for (int t = 0; t < MITER; ++t) {
            int i = i0 + off + t * stride;
            valid[t] = (i < N4);
            v[t] = valid[t] ? __ldcs(&in[base + i]) : make_float4(0.f, 0.f, 0.f, 0.f);
        }
#pragma unroll
        for (int t = 0; t < MITER; ++t) {
            int i = i0 + off + t * stride;
            float4 o;
            float* vp = &v[t].x;
            float* op = &o.x;
#pragma unroll
            for (int c = 0; c < 4; ++c) {
                float f = vp[c];
                bool above = f > Thi;
                op[c] = above ? f : 0.f;
                if (valid[t] && !above && f >= Tlo && cnt < MITER * 4u)
                    lbuf[cnt++] = make_uint2(fkey(f), (unsigned)(i * 4 + c));
            }
            if (valid[t]) __stcs(&out[base + i], o);
        }
    }

    // warp-aggregated candidate flush
    unsigned inc = cnt;
#pragma unroll
    for (int d = 1; d < 32; d <<= 1) {
        unsigned n = __shfl_up_sync(0xffffffffu, inc, d);
        if (lane >= d) inc += n;
    }
    unsigned total = __shfl_sync(0xffffffffu, inc, 31);
    unsigned basepos = 0;
    if (lane == 31 && total) basepos = atomicAdd(&g_candCount[b], total);
    basepos = __shfl_sync(0xffffffffu, basepos, 31);
    unsigned mystart = basepos + inc - cnt;
    for (unsigned j = 0; j < cnt; ++j) {
        unsigned p = mystart + j;
        if (p < CAP) g_cand[b][p] = lbuf[j];
    }
}

// ---------------- K4a: level-2 histogram (bits [20:11]), multi-block ----------------
__global__ void k_hist2() {
    __shared__ unsigned h[1024];
    int tid = threadIdx.x;
    for (int j = tid; j < 1024; j += blockDim.x) h[j] = 0u;
    __syncthreads();
    int b = blockIdx.y;
    unsigned b1 = g_b1[b];
    unsigned m = min(g_candCount[b], CAP);
    int stride = gridDim.x * blockDim.x;
    for (unsigned j = blockIdx.x * blockDim.x + tid; j < m; j += stride) {
        unsigned key = g_cand[b][j].x;
        if ((key >> 21) == b1) atomicAdd(&h[(key >> 11) & 0x3FFu], 1u);
    }
    __syncthreads();
    for (int j = tid; j < 1024; j += blockDim.x)
        if (h[j]) atomicAdd(&g_hist2[b][j], h[j]);
}

// ---------------- K4b: select bucket2 ----------------
__global__ void k_selB2() {
    __shared__ unsigned s[1024];
    int b = blockIdx.x, tid = threadIdx.x;
    unsigned r1 = g_r1[b];
    s[tid] = g_hist2[b][tid];
    __syncthreads();
    for (int off = 1; off < 1024; off <<= 1) {
        unsigned v = (tid + off < 1024) ? s[tid + off] : 0u;
        __syncthreads();
        s[tid] += v;
        __syncthreads();
    }
    unsigned above = (tid == 1023) ? 0u : s[tid + 1];
    if (s[tid] >= r1 && above < r1) { g_b2[b] = (unsigned)tid; g_r2[b] = r1 - above; }
}

// ---------------- K4c: level-3 histogram (bits [10:0]), multi-block ----------------
__global__ void k_hist3() {
    __shared__ unsigned h[2048];
    int tid = threadIdx.x;
    for (int j = tid; j < 2048; j += blockDim.x) h[j] = 0u;
    __syncthreads();
    int b = blockIdx.y;
    unsigned hi21 = (g_b1[b] << 10) | g_b2[b];   // key >> 11 must equal this
    unsigned m = min(g_candCount[b], CAP);
    int stride = gridDim.x * blockDim.x;
    for (unsigned j = blockIdx.x * blockDim.x + tid; j < m; j += stride) {
        unsigned key = g_cand[b][j].x;
        if ((key >> 11) == hi21) atomicAdd(&h[key & 0x7FFu], 1u);
    }
    __syncthreads();
    for (int j = tid; j < 2048; j += blockDim.x)
        if (h[j]) atomicAdd(&g_hist3[b][j], h[j]);
}

// ---------------- K4d: select final bucket -> exact threshold key ----------------
__global__ void k_selB3() {
    __shared__ unsigned s[1024];
    int b = blockIdx.x, tid = threadIdx.x;
    unsigned r2 = g_r2[b];
    s[tid] = g_hist3[b][2 * tid] + g_hist3[b][2 * tid + 1];
    __syncthreads();
    for (int off = 1; off < 1024; off <<= 1) {
        unsigned v = (tid + off < 1024) ? s[tid + off] : 0u;
        __syncthreads();
        s[tid] += v;
        __syncthreads();
    }
    unsigned above = (tid == 1023) ? 0u : s[tid + 1];
    if (s[tid] >= r2 && above < r2) {
        unsigned hi = g_hist3[b][2 * tid + 1];
        unsigned b3, r;
        if (r2 <= above + hi) { b3 = 2u * tid + 1u; r = r2 - above; }
        else                  { b3 = 2u * tid;      r = r2 - above - hi; }
        g_Tkey[b] = (g_b1[b] << 21) | (g_b2[b] << 11) | b3;
        g_r3[b] = r;
    }
}

// ---------------- K5: scatter winners; collect exact-threshold ties ----------------
__global__ void k_fix(float* __restrict__ out, int N) {
    int b = blockIdx.y;
    unsigned count = min(g_candCount[b], CAP);
    unsigned Tkey = g_Tkey[b];
    int stride = gridDim.x * blockDim.x;
    for (unsigned j = blockIdx.x * blockDim.x + threadIdx.x; j < count; j += stride) {
        uint2 e = g_cand[b][j];
        if (e.x > Tkey) {
            out[(size_t)b * (size_t)N + e.y] = keyf(e.x);
        } else if (e.x == Tkey) {
            unsigned p = atomicAdd(&g_eqCount[b], 1u);
            if (p < 4096u) g_eqIdx[b][p] = e.y;
        }
    }
}

// ---------------- K6: tie-break by smallest index (matches lax.top_k) ----------------
__global__ void k_ties(float* __restrict__ out, int N) {
    int b = blockIdx.x, tid = threadIdx.x;
    unsigned ne = min(g_eqCount[b], 4096u);
    unsigned r = g_r3[b];
    float tv = keyf(g_Tkey[b]);
    for (unsigned j = tid; j < ne; j += blockDim.x) {
        unsigned my = g_eqIdx[b][j];
        unsigned rank = 0;
        for (unsigned q = 0; q < ne; ++q) rank += (g_eqIdx[b][q] < my) ? 1u : 0u;
        if (rank < r) out[(size_t)b * (size_t)N + my] = tv;
    }
}

extern "C" void kernel_launch(void* const* d_in, const int* in_sizes, int n_in,
                              void* d_out, int out_size) {
    const float* in = (const float*)d_in[0];
    float* out = (float*)d_out;
    int total = in_sizes[0];
    int N = total / NBATCH;
    int N4 = N / 4;
    unsigned k = (unsigned)(0.1 * (double)N);
    if (k < 1u) k = 1u;

    k_zero<<<16, 1024>>>();
    k_hist<<<dim3(256, NBATCH), 256>>>((const float4*)in, N4);
    k_select1<<<NBATCH, 256>>>(k);
    k_mask<<<dim3(512, NBATCH), 256>>>((const float4*)in, (float4*)out, N4);
    k_hist2<<<dim3(64, NBATCH), 256>>>();
    k_selB2<<<NBATCH, 1024>>>();
    k_hist3<<<dim3(64, NBATCH), 256>>>();
    k_selB3<<<NBATCH, 1024>>>();
    k_fix<<<dim3(128, NBATCH), 256>>>(out, N);
    k_ties<<<NBATCH, 256>>>(out, N);
}